// round 15
// baseline (speedup 1.0000x reference)
#include <cuda_runtime.h>
#include <cuda_fp16.h>
#include <math.h>
#include <stdint.h>

#define MR 2
#define NE 8
#define CD 1024
#define DD 256
#define BB 32
#define SS 512
#define STAGES 6
#define STAGE_BYTES 16384
#define OFF_B  8192
#define RING_BYTES (STAGES * STAGE_BYTES)   // 98304; 2 CTAs/SM

typedef __half fp16;

#define NX4 ((size_t)BB * SS * CD / 4)        // 4194304 float4 groups (x)
#define NW4 ((size_t)MR * NE * CD * DD / 4)   // 1048576 per weight tensor
#define NCVT1 ((int)((NX4 + NW4) / 256))      // 20480 cvt_xdw CTAs
#define NDOWN (8 * BB * MR)                   // 512 down CTAs
#define NUP   (32 * BB * MR)                  // 2048 up CTAs

// ---------------- static device scratch (no allocs) ----------------
__device__ fp16 g_x[(size_t)BB * SS * CD];
__device__ fp16 g_z[(size_t)MR * BB * SS * DD];
__device__ fp16 g_dw16[(size_t)MR * NE * CD * DD];
__device__ fp16 g_uw16[(size_t)MR * NE * DD * CD];
// flags (zero-init; self-resetting each run)
__device__ int g_ready[MR * BB * (SS / 128)];
__device__ int g_done [MR * BB * (SS / 128)];
__device__ int g_c1, g_c2, g_downdone, g_updone;

// ---------------- ptx helpers ----------------
__device__ __forceinline__ uint32_t smem_u32(const void* p) {
    uint32_t a;
    asm("{ .reg .u64 t; cvta.to.shared.u64 t, %1; cvt.u32.u64 %0, t; }" : "=r"(a) : "l"(p));
    return a;
}
#define CP16(dst, src) \
    asm volatile("cp.async.cg.shared.global [%0], [%1], 16;" :: "r"(dst), "l"(src))
#define CP_COMMIT() asm volatile("cp.async.commit_group;")
#define CP_WAIT4()  asm volatile("cp.async.wait_group 4;")
#define CP_WAIT3()  asm volatile("cp.async.wait_group 3;")
#define CP_WAIT2()  asm volatile("cp.async.wait_group 2;")
#define CP_WAIT1()  asm volatile("cp.async.wait_group 1;")
#define CP_WAIT0()  asm volatile("cp.async.wait_group 0;")

#define LDSM4(r, a) \
    asm volatile("ldmatrix.sync.aligned.m8n8.x4.shared.b16 {%0,%1,%2,%3}, [%4];" \
        : "=r"((r)[0]), "=r"((r)[1]), "=r"((r)[2]), "=r"((r)[3]) : "r"(a))
#define LDSM4T(r, a) \
    asm volatile("ldmatrix.sync.aligned.m8n8.x4.trans.shared.b16 {%0,%1,%2,%3}, [%4];" \
        : "=r"((r)[0]), "=r"((r)[1]), "=r"((r)[2]), "=r"((r)[3]) : "r"(a))

#define MMA(d, a, b0, b1) \
    asm volatile("mma.sync.aligned.m16n8k16.row.col.f32.f16.f16.f32 " \
        "{%0,%1,%2,%3},{%4,%5,%6,%7},{%8,%9},{%0,%1,%2,%3};" \
        : "+f"((d)[0]), "+f"((d)[1]), "+f"((d)[2]), "+f"((d)[3]) \
        : "r"((a)[0]), "r"((a)[1]), "r"((a)[2]), "r"((a)[3]), "r"(b0), "r"(b1))

__device__ __forceinline__ uint32_t swz(uint32_t row, uint32_t chunk) {
    return row * 64u + ((chunk ^ ((row >> 1) & 3u)) << 4);
}
__device__ __forceinline__ uint32_t bswz(uint32_t row, uint32_t chunk) {
    return row * 256u + ((chunk ^ (row & 7u)) << 4);
}

__device__ __forceinline__ void cvt4(const float* __restrict__ src, fp16* __restrict__ dst,
                                     size_t i) {
    float4 v = *reinterpret_cast<const float4*>(src + i * 4);
    __half2 p0, p1;
    p0.x = __float2half(v.x); p0.y = __float2half(v.y);
    p1.x = __float2half(v.z); p1.y = __float2half(v.w);
    *reinterpret_cast<uint2*>(dst + i * 4) =
        make_uint2(*reinterpret_cast<uint32_t*>(&p0), *reinterpret_cast<uint32_t*>(&p1));
}

// ---------------- stage loader: 4x cp.async(16B) per thread ----------------
__device__ __forceinline__ void stage_load(uint32_t sbase,
                                           const fp16* __restrict__ A1, int lda,
                                           const fp16* __restrict__ Bg, int ldb,
                                           int ncol0, int kc, int tid) {
    #pragma unroll
    for (int i = 0; i < 2; i++) {
        int q = tid + (i << 8);
        {   int r = q >> 2, c = q & 3;
            CP16(sbase + swz(r, c), A1 + (size_t)r * lda + kc + c * 8); }
        {   int r = q >> 4, c = q & 15;
            CP16(sbase + OFF_B + bswz(r, c),
                 Bg + (size_t)(kc + r) * ldb + ncol0 + c * 8); }
    }
}

// ---------------- GEMM mainloop: warp 64x32; ring=6, lookahead=4 --------------
template <int NK>
__device__ __forceinline__ void gemm_main(uint32_t smem_b,
                                          const fp16* __restrict__ A1, int lda,
                                          const fp16* __restrict__ Bg, int ldb,
                                          int ncol0, float acc[4][4][4], int tid) {
    const int lane = tid & 31, warp = tid >> 5;
    const int wm = (warp & 1) * 64, wn = (warp >> 1) * 32;
    const int r15 = lane & 15, chi = lane >> 4;

    const uint32_t a0 = swz((uint32_t)(wm + r15), (uint32_t)chi);
    const uint32_t b0 = OFF_B + bswz((uint32_t)r15, (uint32_t)((wn >> 3) + chi));
    const uint32_t b1 = OFF_B + bswz((uint32_t)r15, (uint32_t)((wn >> 3) + 2 + chi));

    #pragma unroll
    for (int s = 0; s < 4; s++) {
        stage_load(smem_b + s * STAGE_BYTES, A1, lda, Bg, ldb, ncol0, s * 32, tid);
        CP_COMMIT();
    }

    uint32_t ah[4][4], bb[2][4];
    uint32_t cur = 0, pre = 4 * STAGE_BYTES;

    for (int k = 0; k < NK; k++) {
        if (k + 4 < NK) {
            stage_load(smem_b + pre, A1, lda, Bg, ldb, ncol0, (k + 4) * 32, tid);
            CP_COMMIT();
            pre += STAGE_BYTES; if (pre == RING_BYTES) pre = 0;
        }
        if      (k + 5 <= NK) { CP_WAIT4(); }
        else if (k + 4 <= NK) { CP_WAIT3(); }
        else if (k + 3 <= NK) { CP_WAIT2(); }
        else if (k + 2 <= NK) { CP_WAIT1(); }
        else                  { CP_WAIT0(); }
        __syncthreads();

        const uint32_t stg = smem_b + cur;
        cur += STAGE_BYTES; if (cur == RING_BYTES) cur = 0;

        #pragma unroll
        for (int ks = 0; ks < 2; ks++) {
            const uint32_t ax = stg + (ks ? (a0 ^ 32u) : a0);
            const uint32_t bof = stg + (ks ? 4096u : 0u);
            LDSM4T(bb[0], bof + b0);
            LDSM4T(bb[1], bof + b1);
            LDSM4(ah[0], ax);
            LDSM4(ah[1], ax + 1024);
            LDSM4(ah[2], ax + 2048);
            LDSM4(ah[3], ax + 3072);
            #pragma unroll
            for (int mt = 0; mt < 4; mt++)
                #pragma unroll
                for (int nt = 0; nt < 4; nt++)
                    MMA(acc[mt][nt], ah[mt],
                        bb[nt >> 1][2 * (nt & 1)], bb[nt >> 1][2 * (nt & 1) + 1]);
        }
    }
}

// ---------------- prep: x + dw fp32 -> fp16 (publishes g_c1) ------------------
__global__ void __launch_bounds__(256)
cvt_xdw(const float* __restrict__ x, const float* __restrict__ dw) {
#if __CUDA_ARCH__ >= 900
    if (threadIdx.x == 0) cudaTriggerProgrammaticLaunchCompletion();
#endif
    size_t g = (size_t)blockIdx.x * 256 + threadIdx.x;
    if (g < NX4) cvt4(x, g_x, g);
    else         cvt4(dw, g_dw16, g - NX4);
    __threadfence();
    __syncthreads();
    if (threadIdx.x == 0) atomicAdd(&g_c1, 1);
}

// ---------------- down: converts its uw slice, then z = silu(x@dw+db) ---------
__global__ void __launch_bounds__(256, 2)
down_mma(const int* __restrict__ eidx, const float* __restrict__ db,
         const float* __restrict__ uw) {
    extern __shared__ char smem[];
    uint32_t smem_b = smem_u32(smem);
    const int tid = threadIdx.x, lane = tid & 31, warp = tid >> 5;
    const int wm = (warp & 1) * 64, wn = (warp >> 1) * 32;
    const int stile = blockIdx.x >> 1, ntile = blockIdx.x & 1;
    const int b = blockIdx.y, m = blockIdx.z;

#if __CUDA_ARCH__ >= 900
    if (tid == 0) cudaTriggerProgrammaticLaunchCompletion();
#endif

    // convert this CTA's 1/512 slice of uw (depends only on raw input ->
    // overlaps with cvt_xdw tail and our own g_c1 wait)
    {
        const size_t cta = (size_t)blockIdx.x + 8 * ((size_t)blockIdx.y + BB * blockIdx.z);
        #pragma unroll
        for (int j = 0; j < 8; j++)
            cvt4(uw, g_uw16, cta * 2048 + (size_t)j * 256 + tid);
        __threadfence();
        __syncthreads();
        if (tid == 0) atomicAdd(&g_c2, 1);
    }

    // wait for x + dw conversion
    if (tid == 0) {
        while (atomicAdd(&g_c1, 0) < NCVT1) __nanosleep(128);
    }
    __syncthreads();
    __threadfence();

    const int e = eidx[m * BB + b];
    const fp16* A1 = g_x    + ((size_t)b * SS + stile * 128) * CD;
    const fp16* Bg = g_dw16 + (size_t)(m * NE + e) * CD * DD;

    float acc[4][4][4];
    #pragma unroll
    for (int i = 0; i < 4; i++)
        #pragma unroll
        for (int j = 0; j < 4; j++)
            #pragma unroll
            for (int q = 0; q < 4; q++) acc[i][j][q] = 0.f;

    gemm_main<CD / 32>(smem_b, A1, CD, Bg, DD, ntile * 128, acc, tid);

    const float* bias = db + (size_t)(m * NE + e) * DD;
    const size_t zrow0 = ((size_t)(m * BB + b) * SS + stile * 128);
    const int r0 = lane >> 2, cp = 2 * (lane & 3);

    #pragma unroll
    for (int mt = 0; mt < 4; mt++) {
        #pragma unroll
        for (int nt = 0; nt < 4; nt++) {
            const int col = ntile * 128 + wn + nt * 8 + cp;
            const float2 bv = *reinterpret_cast<const float2*>(bias + col);
            #pragma unroll
            for (int h = 0; h < 2; h++) {
                float v0 = acc[mt][nt][2 * h + 0] + bv.x;
                float v1 = acc[mt][nt][2 * h + 1] + bv.y;
                v0 = v0 / (1.f + __expf(-v0));
                v1 = v1 / (1.f + __expf(-v1));
                __half2 hp; hp.x = __float2half(v0); hp.y = __float2half(v1);
                *reinterpret_cast<__half2*>(
                    g_z + (zrow0 + wm + mt * 16 + r0 + h * 8) * DD + col) = hp;
            }
        }
    }

    __syncthreads();
    if (tid == 0) {
        __threadfence();
        atomicAdd(&g_ready[(m * BB + b) * (SS / 128) + stile], 1);
        int old = atomicAdd(&g_downdone, 1);
        if (old == NDOWN - 1) {        // last down CTA: reset cvt counter
            g_downdone = 0;
            atomicExch(&g_c1, 0);
        }
    }
}

// ---------------- up: out = z @ uw; waits on z flags + uw counter -------------
__global__ void __launch_bounds__(256, 2)
up_mma(const int* __restrict__ eidx, float* __restrict__ out) {
    extern __shared__ char smem[];
    uint32_t smem_b = smem_u32(smem);
    const int tid = threadIdx.x, lane = tid & 31, warp = tid >> 5;
    const int wm = (warp & 1) * 64, wn = (warp >> 1) * 32;
    const int stile = blockIdx.x & 3, ctile = blockIdx.x >> 2;
    const int b = blockIdx.y, m = blockIdx.z;
    const int e = eidx[m * BB + b];
    const int fidx = (m * BB + b) * (SS / 128) + stile;

    if (tid == 0) {
        while (atomicAdd(&g_ready[fidx], 0) < 2 || atomicAdd(&g_c2, 0) < NDOWN)
            __nanosleep(128);
    }
    __syncthreads();
    __threadfence();

    const fp16* A1 = g_z    + ((size_t)(m * BB + b) * SS + stile * 128) * DD;
    const fp16* Bg = g_uw16 + (size_t)(m * NE + e) * DD * CD;

    float acc[4][4][4];
    #pragma unroll
    for (int i = 0; i < 4; i++)
        #pragma unroll
        for (int j = 0; j < 4; j++)
            #pragma unroll
            for (int q = 0; q < 4; q++) acc[i][j][q] = 0.f;

    gemm_main<DD / 32>(smem_b, A1, DD, Bg, CD, ctile * 128, acc, tid);

    const size_t orow0 = ((size_t)(m * BB + b) * SS + stile * 128);
    const int r0 = lane >> 2, cp = 2 * (lane & 3);

    #pragma unroll
    for (int mt = 0; mt < 4; mt++) {
        #pragma unroll
        for (int nt = 0; nt < 4; nt++) {
            const int col = ctile * 128 + wn + nt * 8 + cp;
            #pragma unroll
            for (int h = 0; h < 2; h++) {
                const size_t off = (orow0 + wm + mt * 16 + r0 + h * 8) * CD + col;
                *reinterpret_cast<float2*>(out + off) =
                    make_float2(acc[mt][nt][2 * h + 0], acc[mt][nt][2 * h + 1]);
            }
        }
    }

    if (tid == 0) {
        int old = atomicAdd(&g_done[fidx], 1);
        if (old == (CD / 128) - 1) {
            g_done[fidx] = 0;
            atomicExch(&g_ready[fidx], 0);
        }
        int u = atomicAdd(&g_updone, 1);
        if (u == NUP - 1) {            // last up CTA: reset uw counter
            g_updone = 0;
            atomicExch(&g_c2, 0);
        }
    }
}

// ---------------- launch ------------------------------------------------------
extern "C" void kernel_launch(void* const* d_in, const int* in_sizes, int n_in,
                              void* d_out, int out_size) {
    const float* x    = (const float*)d_in[0];   // [B,S,C]
    const int*   eidx = (const int*)d_in[1];     // [M,B]
    const float* dw   = (const float*)d_in[2];   // [M,N,C,D]
    const float* db   = (const float*)d_in[3];   // [M,N,D]
    const float* uw   = (const float*)d_in[4];   // [M,N,D,C]
    float*       out  = (float*)d_out;           // [M,B,S,C]

    cudaFuncSetAttribute(down_mma, cudaFuncAttributeMaxDynamicSharedMemorySize, RING_BYTES);
    cudaFuncSetAttribute(up_mma,   cudaFuncAttributeMaxDynamicSharedMemorySize, RING_BYTES);

    // 1) x + dw conversion (plain launch: anchors replay ordering)
    cvt_xdw<<<NCVT1, 256>>>(x, dw);

    // 2) down: PDL secondary of cvt_xdw (g_c1 guards data); converts uw slice
    cudaLaunchAttribute attrs[1];
    attrs[0].id = cudaLaunchAttributeProgrammaticStreamSerialization;
    attrs[0].val.programmaticStreamSerializationAllowed = 1;

    cudaLaunchConfig_t cfgd = {};
    cfgd.gridDim = dim3(8, BB, MR);
    cfgd.blockDim = dim3(256, 1, 1);
    cfgd.dynamicSmemBytes = RING_BYTES;
    cfgd.stream = 0;
    cfgd.attrs = attrs;
    cfgd.numAttrs = 1;
    if (cudaLaunchKernelEx(&cfgd, down_mma, eidx, db, uw) != cudaSuccess)
        down_mma<<<dim3(8, BB, MR), 256, RING_BYTES>>>(eidx, db, uw);

    // 3) up: PDL secondary of down (z flags + g_c2 guard data)
    cudaLaunchConfig_t cfgu = {};
    cfgu.gridDim = dim3(32, BB, MR);
    cfgu.blockDim = dim3(256, 1, 1);
    cfgu.dynamicSmemBytes = RING_BYTES;
    cfgu.stream = 0;
    cfgu.attrs = attrs;
    cfgu.numAttrs = 1;
    if (cudaLaunchKernelEx(&cfgu, up_mma, eidx, out) != cudaSuccess)
        up_mma<<<dim3(32, BB, MR), 256, RING_BYTES>>>(eidx, out);
}

// round 16
// speedup vs baseline: 1.0641x; 1.0641x over previous
#include <cuda_runtime.h>
#include <cuda_fp16.h>
#include <math.h>
#include <stdint.h>

#define MR 2
#define NE 8
#define CD 1024
#define DD 256
#define BB 32
#define SS 512
#define STAGES 6
#define STAGE_BYTES 16384
#define OFF_B  8192
#define RING_BYTES (STAGES * STAGE_BYTES)   // 98304; 2 CTAs/SM

typedef __half fp16;

#define NX4 ((size_t)BB * SS * CD / 4)        // 4194304 float4 groups (x)
#define NW4 ((size_t)MR * NE * CD * DD / 4)   // 1048576 per weight tensor
#define NCVT ((int)((NX4 + NW4) / 256))       // 20480 cvt CTAs (x + dw)
#define NDOWN (8 * BB * MR)                   // 512 down CTAs
#define NUP   (32 * BB * MR)                  // 2048 up CTAs

// ---------------- static device scratch (no allocs) ----------------
__device__ fp16 g_x[(size_t)BB * SS * CD];
__device__ fp16 g_z[(size_t)MR * BB * SS * DD];
__device__ fp16 g_dw16[(size_t)MR * NE * CD * DD];
__device__ fp16 g_uw16[(size_t)MR * NE * DD * CD];
// flags (zero-init; self-resetting each run)
__device__ int g_ready[MR * BB * (SS / 128)];
__device__ int g_done [MR * BB * (SS / 128)];
__device__ int g_c2, g_updone;

// ---------------- ptx helpers ----------------
__device__ __forceinline__ uint32_t smem_u32(const void* p) {
    uint32_t a;
    asm("{ .reg .u64 t; cvta.to.shared.u64 t, %1; cvt.u32.u64 %0, t; }" : "=r"(a) : "l"(p));
    return a;
}
#define CP16(dst, src) \
    asm volatile("cp.async.cg.shared.global [%0], [%1], 16;" :: "r"(dst), "l"(src))
#define CP_COMMIT() asm volatile("cp.async.commit_group;")
#define CP_WAIT4()  asm volatile("cp.async.wait_group 4;")
#define CP_WAIT3()  asm volatile("cp.async.wait_group 3;")
#define CP_WAIT2()  asm volatile("cp.async.wait_group 2;")
#define CP_WAIT1()  asm volatile("cp.async.wait_group 1;")
#define CP_WAIT0()  asm volatile("cp.async.wait_group 0;")

#define LDSM4(r, a) \
    asm volatile("ldmatrix.sync.aligned.m8n8.x4.shared.b16 {%0,%1,%2,%3}, [%4];" \
        : "=r"((r)[0]), "=r"((r)[1]), "=r"((r)[2]), "=r"((r)[3]) : "r"(a))
#define LDSM4T(r, a) \
    asm volatile("ldmatrix.sync.aligned.m8n8.x4.trans.shared.b16 {%0,%1,%2,%3}, [%4];" \
        : "=r"((r)[0]), "=r"((r)[1]), "=r"((r)[2]), "=r"((r)[3]) : "r"(a))

#define MMA(d, a, b0, b1) \
    asm volatile("mma.sync.aligned.m16n8k16.row.col.f32.f16.f16.f32 " \
        "{%0,%1,%2,%3},{%4,%5,%6,%7},{%8,%9},{%0,%1,%2,%3};" \
        : "+f"((d)[0]), "+f"((d)[1]), "+f"((d)[2]), "+f"((d)[3]) \
        : "r"((a)[0]), "r"((a)[1]), "r"((a)[2]), "r"((a)[3]), "r"(b0), "r"(b1))

__device__ __forceinline__ uint32_t swz(uint32_t row, uint32_t chunk) {
    return row * 64u + ((chunk ^ ((row >> 1) & 3u)) << 4);
}
__device__ __forceinline__ uint32_t bswz(uint32_t row, uint32_t chunk) {
    return row * 256u + ((chunk ^ (row & 7u)) << 4);
}

__device__ __forceinline__ void cvt4(const float* __restrict__ src, fp16* __restrict__ dst,
                                     size_t i) {
    float4 v = *reinterpret_cast<const float4*>(src + i * 4);
    __half2 p0, p1;
    p0.x = __float2half(v.x); p0.y = __float2half(v.y);
    p1.x = __float2half(v.z); p1.y = __float2half(v.w);
    *reinterpret_cast<uint2*>(dst + i * 4) =
        make_uint2(*reinterpret_cast<uint32_t*>(&p0), *reinterpret_cast<uint32_t*>(&p1));
}

// ---------------- stage loader: 4x cp.async(16B) per thread ----------------
__device__ __forceinline__ void stage_load(uint32_t sbase,
                                           const fp16* __restrict__ A1, int lda,
                                           const fp16* __restrict__ Bg, int ldb,
                                           int ncol0, int kc, int tid) {
    #pragma unroll
    for (int i = 0; i < 2; i++) {
        int q = tid + (i << 8);
        {   int r = q >> 2, c = q & 3;
            CP16(sbase + swz(r, c), A1 + (size_t)r * lda + kc + c * 8); }
        {   int r = q >> 4, c = q & 15;
            CP16(sbase + OFF_B + bswz(r, c),
                 Bg + (size_t)(kc + r) * ldb + ncol0 + c * 8); }
    }
}

// ---------------- GEMM mainloop: warp 64x32; ring=6, lookahead=4 --------------
template <int NK>
__device__ __forceinline__ void gemm_main(uint32_t smem_b,
                                          const fp16* __restrict__ A1, int lda,
                                          const fp16* __restrict__ Bg, int ldb,
                                          int ncol0, float acc[4][4][4], int tid) {
    const int lane = tid & 31, warp = tid >> 5;
    const int wm = (warp & 1) * 64, wn = (warp >> 1) * 32;
    const int r15 = lane & 15, chi = lane >> 4;

    const uint32_t a0 = swz((uint32_t)(wm + r15), (uint32_t)chi);
    const uint32_t b0 = OFF_B + bswz((uint32_t)r15, (uint32_t)((wn >> 3) + chi));
    const uint32_t b1 = OFF_B + bswz((uint32_t)r15, (uint32_t)((wn >> 3) + 2 + chi));

    #pragma unroll
    for (int s = 0; s < 4; s++) {
        stage_load(smem_b + s * STAGE_BYTES, A1, lda, Bg, ldb, ncol0, s * 32, tid);
        CP_COMMIT();
    }

    uint32_t ah[4][4], bb[2][4];
    uint32_t cur = 0, pre = 4 * STAGE_BYTES;

    for (int k = 0; k < NK; k++) {
        if (k + 4 < NK) {
            stage_load(smem_b + pre, A1, lda, Bg, ldb, ncol0, (k + 4) * 32, tid);
            CP_COMMIT();
            pre += STAGE_BYTES; if (pre == RING_BYTES) pre = 0;
        }
        if      (k + 5 <= NK) { CP_WAIT4(); }
        else if (k + 4 <= NK) { CP_WAIT3(); }
        else if (k + 3 <= NK) { CP_WAIT2(); }
        else if (k + 2 <= NK) { CP_WAIT1(); }
        else                  { CP_WAIT0(); }
        __syncthreads();

        const uint32_t stg = smem_b + cur;
        cur += STAGE_BYTES; if (cur == RING_BYTES) cur = 0;

        #pragma unroll
        for (int ks = 0; ks < 2; ks++) {
            const uint32_t ax = stg + (ks ? (a0 ^ 32u) : a0);
            const uint32_t bof = stg + (ks ? 4096u : 0u);
            LDSM4T(bb[0], bof + b0);
            LDSM4T(bb[1], bof + b1);
            LDSM4(ah[0], ax);
            LDSM4(ah[1], ax + 1024);
            LDSM4(ah[2], ax + 2048);
            LDSM4(ah[3], ax + 3072);
            #pragma unroll
            for (int mt = 0; mt < 4; mt++)
                #pragma unroll
                for (int nt = 0; nt < 4; nt++)
                    MMA(acc[mt][nt], ah[mt],
                        bb[nt >> 1][2 * (nt & 1)], bb[nt >> 1][2 * (nt & 1) + 1]);
        }
    }
}

// ---------------- prep: x + dw fp32 -> fp16 (no flags, no fences) -------------
__global__ void __launch_bounds__(256)
cvt_xdw(const float* __restrict__ x, const float* __restrict__ dw) {
    size_t g = (size_t)blockIdx.x * 256 + threadIdx.x;
    if (g < NX4) cvt4(x, g_x, g);
    else         cvt4(dw, g_dw16, g - NX4);
}

// ---------------- down: uw slice cvt (pre-sync), grid-sync, GEMM --------------
__global__ void __launch_bounds__(256, 2)
down_mma(const int* __restrict__ eidx, const float* __restrict__ db,
         const float* __restrict__ uw) {
    extern __shared__ char smem[];
    uint32_t smem_b = smem_u32(smem);
    const int tid = threadIdx.x, lane = tid & 31, warp = tid >> 5;
    const int wm = (warp & 1) * 64, wn = (warp >> 1) * 32;
    const int stile = blockIdx.x >> 1, ntile = blockIdx.x & 1;
    const int b = blockIdx.y, m = blockIdx.z;

#if __CUDA_ARCH__ >= 900
    if (tid == 0) cudaTriggerProgrammaticLaunchCompletion();   // lets up queue
#endif

    // convert this CTA's 1/512 slice of uw: depends ONLY on raw input, so it
    // runs during cvt_xdw's tail, before the grid-dependency sync below.
    {
        const size_t cta = (size_t)blockIdx.x + 8 * ((size_t)blockIdx.y + BB * blockIdx.z);
        #pragma unroll
        for (int j = 0; j < 8; j++)
            cvt4(uw, g_uw16, cta * 2048 + (size_t)j * 256 + tid);
        __threadfence();
        __syncthreads();
        if (tid == 0) atomicAdd(&g_c2, 1);     // 512 atomics total (cheap)
    }

#if __CUDA_ARCH__ >= 900
    cudaGridDependencySynchronize();   // cvt_xdw complete + memory visible
#endif

    const int e = eidx[m * BB + b];
    const fp16* A1 = g_x    + ((size_t)b * SS + stile * 128) * CD;
    const fp16* Bg = g_dw16 + (size_t)(m * NE + e) * CD * DD;

    float acc[4][4][4];
    #pragma unroll
    for (int i = 0; i < 4; i++)
        #pragma unroll
        for (int j = 0; j < 4; j++)
            #pragma unroll
            for (int q = 0; q < 4; q++) acc[i][j][q] = 0.f;

    gemm_main<CD / 32>(smem_b, A1, CD, Bg, DD, ntile * 128, acc, tid);

    const float* bias = db + (size_t)(m * NE + e) * DD;
    const size_t zrow0 = ((size_t)(m * BB + b) * SS + stile * 128);
    const int r0 = lane >> 2, cp = 2 * (lane & 3);

    #pragma unroll
    for (int mt = 0; mt < 4; mt++) {
        #pragma unroll
        for (int nt = 0; nt < 4; nt++) {
            const int col = ntile * 128 + wn + nt * 8 + cp;
            const float2 bv = *reinterpret_cast<const float2*>(bias + col);
            #pragma unroll
            for (int h = 0; h < 2; h++) {
                float v0 = acc[mt][nt][2 * h + 0] + bv.x;
                float v1 = acc[mt][nt][2 * h + 1] + bv.y;
                v0 = v0 / (1.f + __expf(-v0));
                v1 = v1 / (1.f + __expf(-v1));
                __half2 hp; hp.x = __float2half(v0); hp.y = __float2half(v1);
                *reinterpret_cast<__half2*>(
                    g_z + (zrow0 + wm + mt * 16 + r0 + h * 8) * DD + col) = hp;
            }
        }
    }

    __syncthreads();
    if (tid == 0) {
        __threadfence();
        atomicAdd(&g_ready[(m * BB + b) * (SS / 128) + stile], 1);
    }
}

// ---------------- up: out = z @ uw; waits on z flags + uw counter -------------
__global__ void __launch_bounds__(256, 2)
up_mma(const int* __restrict__ eidx, float* __restrict__ out) {
    extern __shared__ char smem[];
    uint32_t smem_b = smem_u32(smem);
    const int tid = threadIdx.x, lane = tid & 31, warp = tid >> 5;
    const int wm = (warp & 1) * 64, wn = (warp >> 1) * 32;
    const int stile = blockIdx.x & 3, ctile = blockIdx.x >> 2;
    const int b = blockIdx.y, m = blockIdx.z;
    const int e = eidx[m * BB + b];
    const int fidx = (m * BB + b) * (SS / 128) + stile;

    if (tid == 0) {
        while (atomicAdd(&g_ready[fidx], 0) < 2 || atomicAdd(&g_c2, 0) < NDOWN)
            __nanosleep(128);
    }
    __syncthreads();
    __threadfence();

    const fp16* A1 = g_z    + ((size_t)(m * BB + b) * SS + stile * 128) * DD;
    const fp16* Bg = g_uw16 + (size_t)(m * NE + e) * DD * CD;

    float acc[4][4][4];
    #pragma unroll
    for (int i = 0; i < 4; i++)
        #pragma unroll
        for (int j = 0; j < 4; j++)
            #pragma unroll
            for (int q = 0; q < 4; q++) acc[i][j][q] = 0.f;

    gemm_main<DD / 32>(smem_b, A1, DD, Bg, CD, ctile * 128, acc, tid);

    const size_t orow0 = ((size_t)(m * BB + b) * SS + stile * 128);
    const int r0 = lane >> 2, cp = 2 * (lane & 3);

    #pragma unroll
    for (int mt = 0; mt < 4; mt++) {
        #pragma unroll
        for (int nt = 0; nt < 4; nt++) {
            const int col = ctile * 128 + wn + nt * 8 + cp;
            #pragma unroll
            for (int h = 0; h < 2; h++) {
                const size_t off = (orow0 + wm + mt * 16 + r0 + h * 8) * CD + col;
                *reinterpret_cast<float2*>(out + off) =
                    make_float2(acc[mt][nt][2 * h + 0], acc[mt][nt][2 * h + 1]);
            }
        }
    }

    // self-reset all flags for clean graph replays
    if (tid == 0) {
        int old = atomicAdd(&g_done[fidx], 1);
        if (old == (CD / 128) - 1) {
            g_done[fidx] = 0;
            atomicExch(&g_ready[fidx], 0);
        }
        int u = atomicAdd(&g_updone, 1);
        if (u == NUP - 1) {
            g_updone = 0;
            atomicExch(&g_c2, 0);
        }
    }
}

// ---------------- launch ------------------------------------------------------
extern "C" void kernel_launch(void* const* d_in, const int* in_sizes, int n_in,
                              void* d_out, int out_size) {
    const float* x    = (const float*)d_in[0];   // [B,S,C]
    const int*   eidx = (const int*)d_in[1];     // [M,B]
    const float* dw   = (const float*)d_in[2];   // [M,N,C,D]
    const float* db   = (const float*)d_in[3];   // [M,N,D]
    const float* uw   = (const float*)d_in[4];   // [M,N,D,C]
    float*       out  = (float*)d_out;           // [M,B,S,C]

    cudaFuncSetAttribute(down_mma, cudaFuncAttributeMaxDynamicSharedMemorySize, RING_BYTES);
    cudaFuncSetAttribute(up_mma,   cudaFuncAttributeMaxDynamicSharedMemorySize, RING_BYTES);

    // 1) x + dw conversion: plain, fast, no signaling overhead
    cvt_xdw<<<NCVT, 256>>>(x, dw);

    cudaLaunchAttribute attrs[1];
    attrs[0].id = cudaLaunchAttributeProgrammaticStreamSerialization;
    attrs[0].val.programmaticStreamSerializationAllowed = 1;

    // 2) down: PDL secondary; converts uw pre-sync, grid-sync guards x/dw
    cudaLaunchConfig_t cfgd = {};
    cfgd.gridDim = dim3(8, BB, MR);
    cfgd.blockDim = dim3(256, 1, 1);
    cfgd.dynamicSmemBytes = RING_BYTES;
    cfgd.stream = 0;
    cfgd.attrs = attrs;
    cfgd.numAttrs = 1;
    if (cudaLaunchKernelEx(&cfgd, down_mma, eidx, db, uw) != cudaSuccess)
        down_mma<<<dim3(8, BB, MR), 256, RING_BYTES>>>(eidx, db, uw);

    // 3) up: PDL secondary of down; z flags + g_c2 guard data
    cudaLaunchConfig_t cfgu = {};
    cfgu.gridDim = dim3(32, BB, MR);
    cfgu.blockDim = dim3(256, 1, 1);
    cfgu.dynamicSmemBytes = RING_BYTES;
    cfgu.stream = 0;
    cfgu.attrs = attrs;
    cfgu.numAttrs = 1;
    if (cudaLaunchKernelEx(&cfgu, up_mma, eidx, out) != cudaSuccess)
        up_mma<<<dim3(32, BB, MR), 256, RING_BYTES>>>(eidx, out);
}

// round 17
// speedup vs baseline: 1.1000x; 1.0337x over previous
#include <cuda_runtime.h>
#include <cuda_fp16.h>
#include <math.h>
#include <stdint.h>

#define MR 2
#define NE 8
#define CD 1024
#define DD 256
#define BB 32
#define SS 512
#define STAGES 6
#define STAGE_BYTES 16384
#define OFF_B  8192
#define RING_BYTES (STAGES * STAGE_BYTES)   // 98304; 2 CTAs/SM

typedef __half fp16;

#define NX4 ((size_t)BB * SS * CD / 4)        // 4194304 float4 groups (x)
#define NW4 ((size_t)MR * NE * CD * DD / 4)   // 1048576 per weight tensor
#define NCVT ((int)((NX4 + NW4) / 512))       // 10240 cvt CTAs (2 float4/thread)
#define NDOWN (8 * BB * MR)                   // 512 down CTAs
#define NUP   (32 * BB * MR)                  // 2048 up CTAs

// ---------------- static device scratch (no allocs) ----------------
__device__ fp16 g_x[(size_t)BB * SS * CD];
__device__ fp16 g_z[(size_t)MR * BB * SS * DD];
__device__ fp16 g_dw16[(size_t)MR * NE * CD * DD];
__device__ fp16 g_uw16[(size_t)MR * NE * DD * CD];
// flags (zero-init; self-resetting each run)
__device__ int g_ready[MR * BB * (SS / 128)];
__device__ int g_done [MR * BB * (SS / 128)];
__device__ int g_c2, g_updone;

// ---------------- ptx helpers ----------------
__device__ __forceinline__ uint32_t smem_u32(const void* p) {
    uint32_t a;
    asm("{ .reg .u64 t; cvta.to.shared.u64 t, %1; cvt.u32.u64 %0, t; }" : "=r"(a) : "l"(p));
    return a;
}
#define CP16(dst, src) \
    asm volatile("cp.async.cg.shared.global [%0], [%1], 16;" :: "r"(dst), "l"(src))
#define CP_COMMIT() asm volatile("cp.async.commit_group;")
#define CP_WAIT4()  asm volatile("cp.async.wait_group 4;")
#define CP_WAIT3()  asm volatile("cp.async.wait_group 3;")
#define CP_WAIT2()  asm volatile("cp.async.wait_group 2;")
#define CP_WAIT1()  asm volatile("cp.async.wait_group 1;")
#define CP_WAIT0()  asm volatile("cp.async.wait_group 0;")

#define LDSM4(r, a) \
    asm volatile("ldmatrix.sync.aligned.m8n8.x4.shared.b16 {%0,%1,%2,%3}, [%4];" \
        : "=r"((r)[0]), "=r"((r)[1]), "=r"((r)[2]), "=r"((r)[3]) : "r"(a))
#define LDSM4T(r, a) \
    asm volatile("ldmatrix.sync.aligned.m8n8.x4.trans.shared.b16 {%0,%1,%2,%3}, [%4];" \
        : "=r"((r)[0]), "=r"((r)[1]), "=r"((r)[2]), "=r"((r)[3]) : "r"(a))

#define MMA(d, a, b0, b1) \
    asm volatile("mma.sync.aligned.m16n8k16.row.col.f32.f16.f16.f32 " \
        "{%0,%1,%2,%3},{%4,%5,%6,%7},{%8,%9},{%0,%1,%2,%3};" \
        : "+f"((d)[0]), "+f"((d)[1]), "+f"((d)[2]), "+f"((d)[3]) \
        : "r"((a)[0]), "r"((a)[1]), "r"((a)[2]), "r"((a)[3]), "r"(b0), "r"(b1))

__device__ __forceinline__ uint32_t swz(uint32_t row, uint32_t chunk) {
    return row * 64u + ((chunk ^ ((row >> 1) & 3u)) << 4);
}
__device__ __forceinline__ uint32_t bswz(uint32_t row, uint32_t chunk) {
    return row * 256u + ((chunk ^ (row & 7u)) << 4);
}

__device__ __forceinline__ void cvt4(const float* __restrict__ src, fp16* __restrict__ dst,
                                     size_t i) {
    float4 v = *reinterpret_cast<const float4*>(src + i * 4);
    __half2 p0, p1;
    p0.x = __float2half(v.x); p0.y = __float2half(v.y);
    p1.x = __float2half(v.z); p1.y = __float2half(v.w);
    *reinterpret_cast<uint2*>(dst + i * 4) =
        make_uint2(*reinterpret_cast<uint32_t*>(&p0), *reinterpret_cast<uint32_t*>(&p1));
}

// ---------------- stage loader: 4x cp.async(16B) per thread ----------------
__device__ __forceinline__ void stage_load(uint32_t sbase,
                                           const fp16* __restrict__ A1, int lda,
                                           const fp16* __restrict__ Bg, int ldb,
                                           int ncol0, int kc, int tid) {
    #pragma unroll
    for (int i = 0; i < 2; i++) {
        int q = tid + (i << 8);
        {   int r = q >> 2, c = q & 3;
            CP16(sbase + swz(r, c), A1 + (size_t)r * lda + kc + c * 8); }
        {   int r = q >> 4, c = q & 15;
            CP16(sbase + OFF_B + bswz(r, c),
                 Bg + (size_t)(kc + r) * ldb + ncol0 + c * 8); }
    }
}

// ---------------- GEMM mainloop: warp 64x32; ring=6, lookahead=4 --------------
template <int NK>
__device__ __forceinline__ void gemm_main(uint32_t smem_b,
                                          const fp16* __restrict__ A1, int lda,
                                          const fp16* __restrict__ Bg, int ldb,
                                          int ncol0, float acc[4][4][4], int tid) {
    const int lane = tid & 31, warp = tid >> 5;
    const int wm = (warp & 1) * 64, wn = (warp >> 1) * 32;
    const int r15 = lane & 15, chi = lane >> 4;

    const uint32_t a0 = swz((uint32_t)(wm + r15), (uint32_t)chi);
    const uint32_t b0 = OFF_B + bswz((uint32_t)r15, (uint32_t)((wn >> 3) + chi));
    const uint32_t b1 = OFF_B + bswz((uint32_t)r15, (uint32_t)((wn >> 3) + 2 + chi));

    #pragma unroll
    for (int s = 0; s < 4; s++) {
        stage_load(smem_b + s * STAGE_BYTES, A1, lda, Bg, ldb, ncol0, s * 32, tid);
        CP_COMMIT();
    }

    uint32_t ah[4][4], bb[2][4];
    uint32_t cur = 0, pre = 4 * STAGE_BYTES;

    for (int k = 0; k < NK; k++) {
        if (k + 4 < NK) {
            stage_load(smem_b + pre, A1, lda, Bg, ldb, ncol0, (k + 4) * 32, tid);
            CP_COMMIT();
            pre += STAGE_BYTES; if (pre == RING_BYTES) pre = 0;
        }
        if      (k + 5 <= NK) { CP_WAIT4(); }
        else if (k + 4 <= NK) { CP_WAIT3(); }
        else if (k + 3 <= NK) { CP_WAIT2(); }
        else if (k + 2 <= NK) { CP_WAIT1(); }
        else                  { CP_WAIT0(); }
        __syncthreads();

        const uint32_t stg = smem_b + cur;
        cur += STAGE_BYTES; if (cur == RING_BYTES) cur = 0;

        #pragma unroll
        for (int ks = 0; ks < 2; ks++) {
            const uint32_t ax = stg + (ks ? (a0 ^ 32u) : a0);
            const uint32_t bof = stg + (ks ? 4096u : 0u);
            LDSM4T(bb[0], bof + b0);
            LDSM4T(bb[1], bof + b1);
            LDSM4(ah[0], ax);
            LDSM4(ah[1], ax + 1024);
            LDSM4(ah[2], ax + 2048);
            LDSM4(ah[3], ax + 3072);
            #pragma unroll
            for (int mt = 0; mt < 4; mt++)
                #pragma unroll
                for (int nt = 0; nt < 4; nt++)
                    MMA(acc[mt][nt], ah[mt],
                        bb[nt >> 1][2 * (nt & 1)], bb[nt >> 1][2 * (nt & 1) + 1]);
        }
    }
}

// ---------------- prep: x + dw fp32 -> fp16; trigger at CTA end ---------------
__global__ void __launch_bounds__(256)
cvt_xdw(const float* __restrict__ x, const float* __restrict__ dw) {
    size_t g0 = ((size_t)blockIdx.x * 256 + threadIdx.x) * 2;   // 2 float4/thread
    #pragma unroll
    for (int j = 0; j < 2; j++) {
        size_t g = g0 + j;
        if (g < NX4) cvt4(x, g_x, g);
        else         cvt4(dw, g_dw16, g - NX4);
    }
#if __CUDA_ARCH__ >= 900
    // after stores: down CTAs become schedulable as cvt's last waves drain;
    // gridsync in down guarantees visibility of all pre-trigger stores.
    cudaTriggerProgrammaticLaunchCompletion();
#endif
}

// ---------------- down: uw slice cvt (pre-sync), grid-sync, GEMM --------------
__global__ void __launch_bounds__(256, 2)
down_mma(const int* __restrict__ eidx, const float* __restrict__ db,
         const float* __restrict__ uw) {
    extern __shared__ char smem[];
    uint32_t smem_b = smem_u32(smem);
    const int tid = threadIdx.x, lane = tid & 31, warp = tid >> 5;
    const int wm = (warp & 1) * 64, wn = (warp >> 1) * 32;
    const int stile = blockIdx.x >> 1, ntile = blockIdx.x & 1;
    const int b = blockIdx.y, m = blockIdx.z;

#if __CUDA_ARCH__ >= 900
    if (tid == 0) cudaTriggerProgrammaticLaunchCompletion();   // lets up queue
#endif

    // convert this CTA's 1/512 slice of uw: depends ONLY on raw input, so it
    // overlaps cvt_xdw's tail (we are scheduled as cvt CTAs retire).
    {
        const size_t cta = (size_t)blockIdx.x + 8 * ((size_t)blockIdx.y + BB * blockIdx.z);
        #pragma unroll
        for (int j = 0; j < 8; j++)
            cvt4(uw, g_uw16, cta * 2048 + (size_t)j * 256 + tid);
        __threadfence();
        __syncthreads();
        if (tid == 0) atomicAdd(&g_c2, 1);     // 512 atomics total (cheap)
    }

#if __CUDA_ARCH__ >= 900
    cudaGridDependencySynchronize();   // cvt_xdw complete + memory visible
#endif

    const int e = eidx[m * BB + b];
    const fp16* A1 = g_x    + ((size_t)b * SS + stile * 128) * CD;
    const fp16* Bg = g_dw16 + (size_t)(m * NE + e) * CD * DD;

    float acc[4][4][4];
    #pragma unroll
    for (int i = 0; i < 4; i++)
        #pragma unroll
        for (int j = 0; j < 4; j++)
            #pragma unroll
            for (int q = 0; q < 4; q++) acc[i][j][q] = 0.f;

    gemm_main<CD / 32>(smem_b, A1, CD, Bg, DD, ntile * 128, acc, tid);

    const float* bias = db + (size_t)(m * NE + e) * DD;
    const size_t zrow0 = ((size_t)(m * BB + b) * SS + stile * 128);
    const int r0 = lane >> 2, cp = 2 * (lane & 3);

    #pragma unroll
    for (int mt = 0; mt < 4; mt++) {
        #pragma unroll
        for (int nt = 0; nt < 4; nt++) {
            const int col = ntile * 128 + wn + nt * 8 + cp;
            const float2 bv = *reinterpret_cast<const float2*>(bias + col);
            #pragma unroll
            for (int h = 0; h < 2; h++) {
                float v0 = acc[mt][nt][2 * h + 0] + bv.x;
                float v1 = acc[mt][nt][2 * h + 1] + bv.y;
                v0 = v0 / (1.f + __expf(-v0));
                v1 = v1 / (1.f + __expf(-v1));
                __half2 hp; hp.x = __float2half(v0); hp.y = __float2half(v1);
                *reinterpret_cast<__half2*>(
                    g_z + (zrow0 + wm + mt * 16 + r0 + h * 8) * DD + col) = hp;
            }
        }
    }

    __syncthreads();
    if (tid == 0) {
        __threadfence();
        atomicAdd(&g_ready[(m * BB + b) * (SS / 128) + stile], 1);
    }
}

// ---------------- up: out = z @ uw; waits on z flags + uw counter -------------
__global__ void __launch_bounds__(256, 2)
up_mma(const int* __restrict__ eidx, float* __restrict__ out) {
    extern __shared__ char smem[];
    uint32_t smem_b = smem_u32(smem);
    const int tid = threadIdx.x, lane = tid & 31, warp = tid >> 5;
    const int wm = (warp & 1) * 64, wn = (warp >> 1) * 32;
    const int stile = blockIdx.x & 3, ctile = blockIdx.x >> 2;
    const int b = blockIdx.y, m = blockIdx.z;
    const int e = eidx[m * BB + b];
    const int fidx = (m * BB + b) * (SS / 128) + stile;

    if (tid == 0) {
        while (atomicAdd(&g_ready[fidx], 0) < 2 || atomicAdd(&g_c2, 0) < NDOWN)
            __nanosleep(128);
    }
    __syncthreads();
    __threadfence();

    const fp16* A1 = g_z    + ((size_t)(m * BB + b) * SS + stile * 128) * DD;
    const fp16* Bg = g_uw16 + (size_t)(m * NE + e) * DD * CD;

    float acc[4][4][4];
    #pragma unroll
    for (int i = 0; i < 4; i++)
        #pragma unroll
        for (int j = 0; j < 4; j++)
            #pragma unroll
            for (int q = 0; q < 4; q++) acc[i][j][q] = 0.f;

    gemm_main<DD / 32>(smem_b, A1, DD, Bg, CD, ctile * 128, acc, tid);

    const size_t orow0 = ((size_t)(m * BB + b) * SS + stile * 128);
    const int r0 = lane >> 2, cp = 2 * (lane & 3);

    #pragma unroll
    for (int mt = 0; mt < 4; mt++) {
        #pragma unroll
        for (int nt = 0; nt < 4; nt++) {
            const int col = ctile * 128 + wn + nt * 8 + cp;
            #pragma unroll
            for (int h = 0; h < 2; h++) {
                const size_t off = (orow0 + wm + mt * 16 + r0 + h * 8) * CD + col;
                *reinterpret_cast<float2*>(out + off) =
                    make_float2(acc[mt][nt][2 * h + 0], acc[mt][nt][2 * h + 1]);
            }
        }
    }

    // self-reset all flags for clean graph replays
    if (tid == 0) {
        int old = atomicAdd(&g_done[fidx], 1);
        if (old == (CD / 128) - 1) {
            g_done[fidx] = 0;
            atomicExch(&g_ready[fidx], 0);
        }
        int u = atomicAdd(&g_updone, 1);
        if (u == NUP - 1) {
            g_updone = 0;
            atomicExch(&g_c2, 0);
        }
    }
}

// ---------------- launch ------------------------------------------------------
extern "C" void kernel_launch(void* const* d_in, const int* in_sizes, int n_in,
                              void* d_out, int out_size) {
    const float* x    = (const float*)d_in[0];   // [B,S,C]
    const int*   eidx = (const int*)d_in[1];     // [M,B]
    const float* dw   = (const float*)d_in[2];   // [M,N,C,D]
    const float* db   = (const float*)d_in[3];   // [M,N,D]
    const float* uw   = (const float*)d_in[4];   // [M,N,D,C]
    float*       out  = (float*)d_out;           // [M,B,S,C]

    cudaFuncSetAttribute(down_mma, cudaFuncAttributeMaxDynamicSharedMemorySize, RING_BYTES);
    cudaFuncSetAttribute(up_mma,   cudaFuncAttributeMaxDynamicSharedMemorySize, RING_BYTES);

    // 1) x + dw conversion; each CTA triggers after its stores
    cvt_xdw<<<NCVT, 256>>>(x, dw);

    cudaLaunchAttribute attrs[1];
    attrs[0].id = cudaLaunchAttributeProgrammaticStreamSerialization;
    attrs[0].val.programmaticStreamSerializationAllowed = 1;

    // 2) down: PDL secondary of cvt; converts uw pre-sync, grid-sync guards x/dw
    cudaLaunchConfig_t cfgd = {};
    cfgd.gridDim = dim3(8, BB, MR);
    cfgd.blockDim = dim3(256, 1, 1);
    cfgd.dynamicSmemBytes = RING_BYTES;
    cfgd.stream = 0;
    cfgd.attrs = attrs;
    cfgd.numAttrs = 1;
    if (cudaLaunchKernelEx(&cfgd, down_mma, eidx, db, uw) != cudaSuccess)
        down_mma<<<dim3(8, BB, MR), 256, RING_BYTES>>>(eidx, db, uw);

    // 3) up: PDL secondary of down; z flags + g_c2 guard data
    cudaLaunchConfig_t cfgu = {};
    cfgu.gridDim = dim3(32, BB, MR);
    cfgu.blockDim = dim3(256, 1, 1);
    cfgu.dynamicSmemBytes = RING_BYTES;
    cfgu.stream = 0;
    cfgu.attrs = attrs;
    cfgu.numAttrs = 1;
    if (cudaLaunchKernelEx(&cfgu, up_mma, eidx, out) != cudaSuccess)
        up_mma<<<dim3(32, BB, MR), 256, RING_BYTES>>>(eidx, out);
}